// round 15
// baseline (speedup 1.0000x reference)
#include <cuda_runtime.h>
#include <cuda_bf16.h>
#include <math.h>
#include <stdint.h>

// ---------------------------------------------------------------------------
// Problem constants
// ---------------------------------------------------------------------------
#define T_LEN 512
#define B_SZ  64
#define HID   512
#define G4    2048          // 4*HID (gate rows)
#define CTXD  792
#define INDIM 1048

// ---------------------------------------------------------------------------
// Device scratch
// ---------------------------------------------------------------------------
__device__ float d_gctx[B_SZ * G4];                               // [b][g]
__device__ float d_P[260 * 8 * G4];                               // [(v*8+j)][g]
__device__ float d_gx0[(size_t)T_LEN * B_SZ * G4];                // [t][b][g]
__device__ float d_gx1[(size_t)T_LEN * B_SZ * G4];                // [t][b][g]

// hidden state, bf16 hi/lo split, layout [t+1][b][k] (slab 0 = zeros).
__device__ __nv_bfloat16 d_h1hi[(size_t)(T_LEN + 1) * B_SZ * HID];
__device__ __nv_bfloat16 d_h1lo[(size_t)(T_LEN + 1) * B_SZ * HID];
__device__ __nv_bfloat16 d_h2hi[(size_t)(T_LEN + 1) * B_SZ * HID];
__device__ __nv_bfloat16 d_h2lo[(size_t)(T_LEN + 1) * B_SZ * HID];

// bf16-split weights for the big GEMMs
__device__ __nv_bfloat16 d_W1hi[2048 * 512], d_W1lo[2048 * 512];  // W_ih1
__device__ __nv_bfloat16 d_Wohi[256 * 512],  d_Wolo[256 * 512];   // W_out

// per-CTA tiled W_hh images for the recurrence
__device__ __nv_bfloat16 d_WThi[2 * 128 * 8192];
__device__ __nv_bfloat16 d_WTlo[2 * 128 * 8192];

// Two-level barrier state for 128 CTAs. All counters MONOTONIC (mask checks,
// no resets) => deterministic under graph replay. 16 leaf counters 256B apart
// so arrival atomics serialize 8-deep (parallel across 16 LTS lines) instead
// of 128-deep on one line (~3.5K cyc/step exposed now that the MMA step is
// short — this was hidden under the long fp32 compute tail in R4-R8).
__device__ unsigned g_leaf[16 * 64];     // stride 64 uints = 256B
__device__ unsigned g_root = 0;
__device__ volatile unsigned g_gen = 0;

// ---------------------------------------------------------------------------
// Tree grid barrier for 128 co-resident CTAs (rec_tc)
// ---------------------------------------------------------------------------
__device__ __forceinline__ void grid_sync128() {
    __syncthreads();
    if (threadIdx.x == 0) {
        unsigned my = g_gen;                         // read BEFORE arriving
        __threadfence();                             // publish h stores
        bool released = false;
        if ((atomicAdd(&g_leaf[(blockIdx.x >> 3) * 64], 1u) & 7u) == 7u) {
            if ((atomicAdd(&g_root, 1u) & 15u) == 15u) {
                __threadfence();
                g_gen = my + 1;                      // release
                released = true;
            }
        }
        if (!released) while (g_gen == my) { }       // volatile spin
    }
    __syncthreads();
}

// fast, safe pointwise helpers
__device__ __forceinline__ float sigm(float x) {
    x = fminf(fmaxf(x, -30.f), 30.f);
    return __fdividef(1.f, 1.f + __expf(-x));
}
__device__ __forceinline__ float tanh_f(float x) {
    x = fminf(fmaxf(x, -15.f), 15.f);
    float e = __expf(-2.f * x);
    return (1.f - e) * __fdividef(1.f, 1.f + e);
}

// ---------------------------------------------------------------------------
// warp-level tensor-core + cp.async helpers (base PTX ISA, compute_103-safe)
// ---------------------------------------------------------------------------
__device__ __forceinline__ uint32_t smem_u32(const void* p) {
    uint32_t a;
    asm("{ .reg .u64 t; cvta.to.shared.u64 t, %1; cvt.u32.u64 %0, t; }" : "=r"(a) : "l"(p));
    return a;
}
__device__ __forceinline__ void ldm_x4(uint32_t* r, uint32_t addr) {
    asm volatile("ldmatrix.sync.aligned.m8n8.x4.shared.b16 {%0,%1,%2,%3}, [%4];"
        : "=r"(r[0]), "=r"(r[1]), "=r"(r[2]), "=r"(r[3]) : "r"(addr));
}
__device__ __forceinline__ void hmma(float* d, const uint32_t* a, const uint32_t* b) {
    asm volatile("mma.sync.aligned.m16n8k16.row.col.f32.bf16.bf16.f32 "
        "{%0,%1,%2,%3}, {%4,%5,%6,%7}, {%8,%9}, {%0,%1,%2,%3};"
        : "+f"(d[0]), "+f"(d[1]), "+f"(d[2]), "+f"(d[3])
        : "r"(a[0]), "r"(a[1]), "r"(a[2]), "r"(a[3]), "r"(b[0]), "r"(b[1]));
}
#define CP_ASYNC16(dst, src) \
    asm volatile("cp.async.cg.shared.global [%0], [%1], 16;" :: "r"(dst), "l"(src) : "memory")
#define CP_COMMIT() asm volatile("cp.async.commit_group;" ::: "memory")
#define CP_WAIT(N)  asm volatile("cp.async.wait_group %0;" :: "n"(N) : "memory")

// smem tile geometry: rows of 32 bf16 (64B), 16B chunks swizzled.
__device__ __forceinline__ uint32_t swz_off(int row, int c16) {
    return (uint32_t)(row * 64 + ((c16 ^ ((row >> 1) & 3)) << 4));
}
__device__ __forceinline__ uint32_t frag_addr(uint32_t sbase, int row0, int kk, int lane) {
    int row = row0 + (lane & 7) + ((lane >> 3) & 1) * 8;
    int c16 = (kk >> 3) + (lane >> 4);
    return sbase + swz_off(row, c16);
}

// ---------------------------------------------------------------------------
// K0: zero t=0 slabs of all hidden-state buffers
// ---------------------------------------------------------------------------
__global__ void zero_h0_kernel() {
    int i = blockIdx.x * blockDim.x + threadIdx.x;
    if (i < HID * B_SZ) {
        __nv_bfloat16 z = __float2bfloat16(0.f);
        d_h1hi[i] = z; d_h1lo[i] = z; d_h2hi[i] = z; d_h2lo[i] = z;
    }
}

// ---------------------------------------------------------------------------
// K1: gctx
// ---------------------------------------------------------------------------
__global__ __launch_bounds__(256) void gctx_kernel(
    const float* __restrict__ conv, const int* __restrict__ cat,
    const float* __restrict__ num, const float* __restrict__ ce0,
    const float* __restrict__ ce1, const float* __restrict__ ce2,
    const float* __restrict__ W_ih0, const float* __restrict__ b_ih0,
    const float* __restrict__ b_hh0)
{
    __shared__ __align__(16) float ctx[CTXD];
    int b = blockIdx.x, tid = threadIdx.x;
    int i0 = cat[b * 3 + 0], i1 = cat[b * 3 + 1], i2 = cat[b * 3 + 2];
    for (int i = tid; i < 512; i += 256) ctx[i]       = conv[b * 512 + i];
    for (int i = tid; i < 50;  i += 256) ctx[512 + i] = ce0[i0 * 50 + i];
    for (int i = tid; i < 64;  i += 256) ctx[562 + i] = ce1[i1 * 64 + i];
    for (int i = tid; i < 150; i += 256) ctx[626 + i] = ce2[i2 * 150 + i];
    for (int i = tid; i < 16;  i += 256) ctx[776 + i] = num[b * 16 + i];
    __syncthreads();
    const float4* cv = (const float4*)ctx;
    for (int g = tid; g < G4; g += 256) {
        const float4* wr = (const float4*)(W_ih0 + (size_t)g * INDIM);
        float acc = b_ih0[g] + b_hh0[g];
        #pragma unroll 4
        for (int kk = 0; kk < 198; ++kk) {
            float4 w = wr[kk], c4 = cv[kk];
            acc = fmaf(w.x, c4.x, fmaf(w.y, c4.y, fmaf(w.z, c4.z, fmaf(w.w, c4.w, acc))));
        }
        d_gctx[b * G4 + g] = acc;
    }
}

// ---------------------------------------------------------------------------
// K2: byte projection table
// ---------------------------------------------------------------------------
__global__ __launch_bounds__(256) void ptable_kernel(
    const float* __restrict__ byte_emb, const float* __restrict__ W_ih0)
{
    int pid = blockIdx.x;
    int v = pid >> 3, j = pid & 7;
    __shared__ float e[32];
    if (threadIdx.x < 32) e[threadIdx.x] = byte_emb[v * 32 + threadIdx.x];
    __syncthreads();
    for (int g = threadIdx.x; g < G4; g += 256) {
        const float* wr = W_ih0 + (size_t)g * INDIM + CTXD + j * 32;
        float acc = 0.f;
        #pragma unroll
        for (int d = 0; d < 32; ++d) acc = fmaf(e[d], wr[d], acc);
        d_P[(size_t)pid * G4 + g] = acc;
    }
}

// ---------------------------------------------------------------------------
// K3: gx0 assembly via gathers
// ---------------------------------------------------------------------------
__global__ __launch_bounds__(128) void gx0_kernel(const int* __restrict__ payload)
{
    int t = blockIdx.x, b = blockIdx.y, tid = threadIdx.x;
    __shared__ int rows[8];
    if (tid < 8) {
        int q = t + tid;
        int v = (q < 7) ? 256 : ((q == 7) ? 257 : payload[b * 512 + (q - 8)]);
        rows[tid] = v * 8 + tid;
    }
    __syncthreads();
    float4* outp = (float4*)(d_gx0 + ((size_t)t * B_SZ + b) * G4);
    const float4* gc = (const float4*)(d_gctx + b * G4);
    #pragma unroll
    for (int p = 0; p < 4; ++p) {
        int g4 = p * 128 + tid;
        float4 acc = gc[g4];
        #pragma unroll
        for (int j = 0; j < 8; ++j) {
            float4 pv = ((const float4*)(d_P + (size_t)rows[j] * G4))[g4];
            acc.x += pv.x; acc.y += pv.y; acc.z += pv.z; acc.w += pv.w;
        }
        outp[g4] = acc;
    }
}

// ---------------------------------------------------------------------------
// KW: fp32 weights -> bf16 hi/lo split. which: 0=W_ih1, 1=W_out.
// ---------------------------------------------------------------------------
__global__ __launch_bounds__(256) void convw_kernel(
    const float* __restrict__ W, int which, int n)
{
    __nv_bfloat16* hi = which ? d_Wohi : d_W1hi;
    __nv_bfloat16* lo = which ? d_Wolo : d_W1lo;
    int i = blockIdx.x * 256 + threadIdx.x;
    if (i < n) {
        float x = W[i];
        __nv_bfloat16 h = __float2bfloat16(x);
        hi[i] = h;
        lo[i] = __float2bfloat16(x - __bfloat162float(h));
    }
}

// ---------------------------------------------------------------------------
// KWT: W_hh -> per-CTA tiled bf16 hi/lo images for rec_tc.
// ---------------------------------------------------------------------------
__global__ __launch_bounds__(256) void convwhh_kernel(
    const float* __restrict__ Whh, int layer)
{
    int idx = blockIdx.x * 256 + threadIdx.x;    // [0, 131072)
    int c = idx >> 10, rem = idx & 1023;
    int r = rem >> 6, rem2 = rem & 63;
    int ch = rem2 >> 2, c16 = rem2 & 3;
    int g = r >> 2, u = r & 3;
    const float* src = Whh + ((size_t)(g * 512 + c * 4 + u)) * 512 + ch * 32 + c16 * 8;
    float4 v0 = *(const float4*)src;
    float4 v1 = *(const float4*)(src + 4);
    float x[8] = {v0.x, v0.y, v0.z, v0.w, v1.x, v1.y, v1.z, v1.w};
    ushort hs[8], ls[8];
    #pragma unroll
    for (int i = 0; i < 8; ++i) {
        __nv_bfloat16 h = __float2bfloat16(x[i]);
        __nv_bfloat16 l = __float2bfloat16(x[i] - __bfloat162float(h));
        hs[i] = __bfloat16_as_ushort(h);
        ls[i] = __bfloat16_as_ushort(l);
    }
    size_t dst = ((size_t)layer * 128 + c) * 16384 + ch * 1024 + swz_off(r, c16);
    uint4 ph, pl;
    ph.x = hs[0] | ((uint32_t)hs[1] << 16); ph.y = hs[2] | ((uint32_t)hs[3] << 16);
    ph.z = hs[4] | ((uint32_t)hs[5] << 16); ph.w = hs[6] | ((uint32_t)hs[7] << 16);
    pl.x = ls[0] | ((uint32_t)ls[1] << 16); pl.y = ls[2] | ((uint32_t)ls[3] << 16);
    pl.z = ls[4] | ((uint32_t)ls[5] << 16); pl.w = ls[6] | ((uint32_t)ls[7] << 16);
    *(uint4*)((uint8_t*)d_WThi + dst) = ph;
    *(uint4*)((uint8_t*)d_WTlo + dst) = pl;
}

// ---------------------------------------------------------------------------
// K4/K6: tensor-core persistent LSTM recurrence (R13 + tree barrier + gx
// smem staging). 128 CTAs x 128 threads, 165KB smem.
// ---------------------------------------------------------------------------
#define RQ_OFF 163840      // gx staging tile: float[64][5 float4] = 5120 B

__global__ __launch_bounds__(128, 1) void rec_tc_kernel(int layer)
{
    extern __shared__ __align__(16) uint8_t sm[];
    uint8_t* sAh = sm;                 // 16 KB
    uint8_t* sAl = sm + 16384;         // 16 KB
    uint8_t* sBh = sm + 32768;         // 64 KB: [16 ch][64 b][64B]
    uint8_t* sBl = sm + 98304;         // 64 KB
    float*   sQ  = (float*)(sm + RQ_OFF);  // [b][g] float4 rows, stride 5

    const float* gx = layer ? d_gx1 : d_gx0;
    __nv_bfloat16* hhi = layer ? d_h2hi : d_h1hi;
    __nv_bfloat16* hlo = layer ? d_h2lo : d_h1lo;

    int tid = threadIdx.x, lane = tid & 31, w = tid >> 5;
    int blk = blockIdx.x;

    // stationary A tiles (already tile-formatted by convwhh)
    {
        const uint4* srcH = (const uint4*)(d_WThi + ((size_t)layer * 128 + blk) * 8192);
        const uint4* srcL = (const uint4*)(d_WTlo + ((size_t)layer * 128 + blk) * 8192);
        for (int i = tid; i < 1024; i += 128) {
            ((uint4*)sAh)[i] = srcH[i];
            ((uint4*)sAl)[i] = srcL[i];
        }
    }

    uint32_t bAh = smem_u32(sAh), bAl = smem_u32(sAl);
    uint32_t bBh = smem_u32(sBh), bBl = smem_u32(sBl);

    int r = lane >> 2;                 // D row group (0..7)
    int cp = lane & 3;                 // batch pair within n-tile
    bool pw = (r < 4);                 // pointwise-owning lanes (i,g rows)
    int uglob = blk * 4 + r;           // this lane's unit (when pw)

    float cst[2][2] = {};              // cell state [nt][batch 0/1]

    for (int t = 0; t < T_LEN; ++t) {
        grid_sync128();                // h[t] fully published by all CTAs
        const uint8_t* srcHi = (const uint8_t*)hhi + (size_t)t * 65536;
        const uint8_t* srcLo = (const uint8_t*)hlo + (size_t)t * 65536;

        // issue all B-tile cp.asyncs in 4 quarter-groups (chunks 4q..4q+4)
        #pragma unroll
        for (int qq = 0; qq < 4; ++qq) {
            #pragma unroll
            for (int i = 0; i < 8; ++i) {
                int idx = tid + i * 128;                 // [0,1024)
                int b = idx >> 4, chl = (idx >> 2) & 3, c16 = idx & 3;
                int ch = qq * 4 + chl;
                uint32_t so = (uint32_t)(b * 1024 + ch * 64 + c16 * 16);
                uint32_t dofs = ch * 4096 + swz_off(b, c16);
                CP_ASYNC16(bBh + dofs, srcHi + so);
                CP_ASYNC16(bBl + dofs, srcLo + so);
            }
            CP_COMMIT();
        }

        // stage gx gate inputs: 256 coalesced LDG.128 -> smem (replaces 1024
        // scattered LDG.32 from the pointwise lanes; completes under the MMA)
        #pragma unroll
        for (int i = 0; i < 2; ++i) {
            int idx = tid + i * 128;                     // [0,256)
            int b = idx >> 2, g = idx & 3;
            float4 v = *(const float4*)(gx + ((size_t)t * B_SZ + b) * G4
                                           + g * 512 + blk * 4);
            *(float4*)&sQ[(b * 5 + g) * 4] = v;
        }

        float acc[2][4] = {};

        // MMA quarters, overlapped with the remaining cp.async streams
        #pragma unroll
        for (int qq = 0; qq < 4; ++qq) {
            if (qq == 0) CP_WAIT(3);
            else if (qq == 1) CP_WAIT(2);
            else if (qq == 2) CP_WAIT(1);
            else CP_WAIT(0);
            __syncthreads();
            #pragma unroll
            for (int chl = 0; chl < 4; ++chl) {
                int ch = qq * 4 + chl;
                #pragma unroll
                for (int kk = 0; kk < 32; kk += 16) {
                    uint32_t aH[4], aL[4], rr[4];
                    ldm_x4(aH, frag_addr(bAh + ch * 1024, 0, kk, lane));
                    ldm_x4(aL, frag_addr(bAl + ch * 1024, 0, kk, lane));
                    uint32_t bH[2][2], bL[2][2];
                    ldm_x4(rr, frag_addr(bBh + ch * 4096, w * 16, kk, lane));
                    bH[0][0] = rr[0]; bH[0][1] = rr[2];
                    bH[1][0] = rr[1]; bH[1][1] = rr[3];
                    ldm_x4(rr, frag_addr(bBl + ch * 4096, w * 16, kk, lane));
                    bL[0][0] = rr[0]; bL[0][1] = rr[2];
                    bL[1][0] = rr[1]; bL[1][1] = rr[3];
                    #pragma unroll
                    for (int nt = 0; nt < 2; ++nt) {
                        hmma(acc[nt], aH, bH[nt]);
                        hmma(acc[nt], aH, bL[nt]);
                        hmma(acc[nt], aL, bH[nt]);
                    }
                }
            }
        }
        __syncthreads();   // B tiles + sQ ready/free; all MMA done

        // pointwise: lanes<16 have i (acc[nt][0..1]) and g (acc[nt][2..3]);
        // partner lane+16 has f and o for the same unit/batches.
        #pragma unroll
        for (int nt = 0; nt < 2; ++nt) {
            float f0 = __shfl_xor_sync(0xffffffffu, acc[nt][0], 16);
            float f1 = __shfl_xor_sync(0xffffffffu, acc[nt][1], 16);
            float o0 = __shfl_xor_sync(0xffffffffu, acc[nt][2], 16);
            float o1 = __shfl_xor_sync(0xffffffffu, acc[nt][3], 16);
            if (pw) {
                int b0 = w * 16 + nt * 8 + cp * 2;
                const float* q0 = &sQ[(b0 * 5) * 4 + r];         // [g] stride 4
                const float* q1 = &sQ[((b0 + 1) * 5) * 4 + r];
                float gi0 = acc[nt][0] + q0[0];
                float gf0 = f0          + q0[4];
                float gg0 = acc[nt][2] + q0[8];
                float go0 = o0          + q0[12];
                float gi1 = acc[nt][1] + q1[0];
                float gf1 = f1          + q1[4];
                float gg1 = acc[nt][3] + q1[8];
                float go1 = o1          + q1[12];
                cst[nt][0] = fmaf(sigm(gf0), cst[nt][0], sigm(gi0) * tanh_f(gg0));
                cst[nt][1] = fmaf(sigm(gf1), cst[nt][1], sigm(gi1) * tanh_f(gg1));
                float h0 = sigm(go0) * tanh_f(cst[nt][0]);
                float h1 = sigm(go1) * tanh_f(cst[nt][1]);
                size_t base = (size_t)(t + 1) * 32768 + (size_t)b0 * 512 + uglob;
                __nv_bfloat16 hh0 = __float2bfloat16(h0);
                __nv_bfloat16 hh1 = __float2bfloat16(h1);
                hhi[base]       = hh0;
                hlo[base]       = __float2bfloat16(h0 - __bfloat162float(hh0));
                hhi[base + 512] = hh1;
                hlo[base + 512] = __float2bfloat16(h1 - __bfloat162float(hh1));
            }
        }
    }
}

// ---------------------------------------------------------------------------
// KG: warp-tiled bf16-split mma.sync GEMM (R12-proven).
// mode 0: A=h1, B=W_ih1, out = d_gx1 + bias1+bias2
// mode 1: A=h2, B=W_out, out = outp  + bias1
// ---------------------------------------------------------------------------
__global__ __launch_bounds__(256) void mma_gemm_kernel(
    const float* __restrict__ bias1, const float* __restrict__ bias2,
    float* __restrict__ outp, int mode)
{
    __shared__ __align__(16) uint8_t sAh[8192], sAl[8192], sBh[8192], sBl[8192];

    int tid = threadIdx.x, lane = tid & 31, wid = tid >> 5;
    int mw = wid & 3, nw = wid >> 2;
    int n0 = blockIdx.x * 128, tp = blockIdx.y;

    uint32_t bAh = smem_u32(sAh), bAl = smem_u32(sAl);
    uint32_t bBh = smem_u32(sBh), bBl = smem_u32(sBl);

    const __nv_bfloat16* Ah = (mode ? d_h2hi : d_h1hi) + (size_t)(2 * tp + 1) * 32768;
    const __nv_bfloat16* Al = (mode ? d_h2lo : d_h1lo) + (size_t)(2 * tp + 1) * 32768;
    const __nv_bfloat16* Bh = (mode ? d_Wohi : d_W1hi) + (size_t)n0 * 512;
    const __nv_bfloat16* Bl = (mode ? d_Wolo : d_W1lo) + (size_t)n0 * 512;

    float acc[2][8][4] = {};

    int r0t = tid >> 2,          c0t = tid & 3;
    int r1t = (tid + 256) >> 2,  c1t = tid & 3;
    uint32_t d0 = swz_off(r0t, c0t), d1 = swz_off(r1t, c1t);

    for (int kc = 0; kc < 512; kc += 32) {
        uint4 vah0 = *(const uint4*)(Ah + (size_t)r0t * 512 + kc + c0t * 8);
        uint4 vah1 = *(const uint4*)(Ah + (size_t)r1t * 512 + kc + c1t * 8);
        uint4 val0 = *(const uint4*)(Al + (size_t)r0t * 512 + kc + c0t * 8);
        uint4 val1 = *(const uint4*)(Al + (size_t)r1t * 512 + kc + c1t * 8);
        uint4 vbh0 = *(const uint4*)(Bh + (size_t)r0t * 512 + kc + c0t * 8);
        uint4 vbh1 = *(const uint4*)(Bh + (size_t)r1t * 512 + kc + c1t * 8);
        uint4 vbl0 = *(const uint4*)(Bl + (size_t)r0t * 512 + kc + c0t * 8);
        uint4 vbl1 = *(const uint4*)(Bl + (size_t)r1t * 512 + kc + c1t * 8);

        __syncthreads();
        *(uint4*)(sAh + d0) = vah0;  *(uint4*)(sAh + d1) = vah1;
        *(uint4*)(sAl + d0) = val0;  *(uint4*)(sAl + d1) = val1;
        *(uint4*)(sBh + d0) = vbh0;  *(uint4*)(sBh + d1) = vbh1;
        *(uint4*)(sBl + d0) = vbl0;  *(uint4*)(sBl + d1) = vbl1;
        __syncthreads();

        #pragma unroll
        for (int kk = 0; kk < 32; kk += 16) {
            uint32_t aH[2][4], aL[2][4], bb[8][2];
            #pragma unroll
            for (int mt = 0; mt < 2; ++mt) {
                ldm_x4(aH[mt], frag_addr(bAh, mw * 32 + mt * 16, kk, lane));
                ldm_x4(aL[mt], frag_addr(bAl, mw * 32 + mt * 16, kk, lane));
            }
            #pragma unroll
            for (int q = 0; q < 4; ++q) {
                uint32_t rr[4];
                ldm_x4(rr, frag_addr(bBh, nw * 64 + q * 16, kk, lane));
                bb[2 * q][0] = rr[0]; bb[2 * q][1] = rr[2];
                bb[2 * q + 1][0] = rr[1]; bb[2 * q + 1][1] = rr[3];
            }
            #pragma unroll
            for (int mt = 0; mt < 2; ++mt)
                #pragma unroll
                for (int nt = 0; nt < 8; ++nt) {
                    hmma(acc[mt][nt], aH[mt], bb[nt]);
                    hmma(acc[mt][nt], aL[mt], bb[nt]);
                }
            #pragma unroll
            for (int q = 0; q < 4; ++q) {
                uint32_t rr[4];
                ldm_x4(rr, frag_addr(bBl, nw * 64 + q * 16, kk, lane));
                bb[2 * q][0] = rr[0]; bb[2 * q][1] = rr[2];
                bb[2 * q + 1][0] = rr[1]; bb[2 * q + 1][1] = rr[3];
            }
            #pragma unroll
            for (int mt = 0; mt < 2; ++mt)
                #pragma unroll
                for (int nt = 0; nt < 8; ++nt)
                    hmma(acc[mt][nt], aH[mt], bb[nt]);
        }
    }

    int gr = lane >> 2, gc2 = (lane & 3) * 2;
    #pragma unroll
    for (int mt = 0; mt < 2; ++mt) {
        #pragma unroll
        for (int half = 0; half < 2; ++half) {
            int row = mw * 32 + mt * 16 + gr + half * 8;
            int t = tp * 2 + (row >> 6), b = row & 63;
            #pragma unroll
            for (int nt = 0; nt < 8; ++nt) {
                int col = n0 + nw * 64 + nt * 8 + gc2;
                float z0 = bias1[col], z1 = bias1[col + 1];
                if (mode == 0) { z0 += bias2[col]; z1 += bias2[col + 1]; }
                float2 st = make_float2(acc[mt][nt][half * 2 + 0] + z0,
                                        acc[mt][nt][half * 2 + 1] + z1);
                if (mode == 0)
                    *(float2*)(d_gx1 + ((size_t)t * B_SZ + b) * G4 + col) = st;
                else
                    *(float2*)(outp + ((size_t)b * T_LEN + t) * 256 + col) = st;
            }
        }
    }
}

// ---------------------------------------------------------------------------
// kernel_launch
// ---------------------------------------------------------------------------
extern "C" void kernel_launch(void* const* d_in, const int* in_sizes, int n_in,
                              void* d_out, int out_size) {
    const float* ecc     = (const float*)d_in[0];
    const int*   cat     = (const int*)  d_in[1];
    const float* num     = (const float*)d_in[2];
    const int*   payload = (const int*)  d_in[3];
    const float* ce0     = (const float*)d_in[4];
    const float* ce1     = (const float*)d_in[5];
    const float* ce2     = (const float*)d_in[6];
    const float* bemb    = (const float*)d_in[7];
    const float* W_ih0   = (const float*)d_in[8];
    const float* W_hh0   = (const float*)d_in[9];
    const float* b_ih0   = (const float*)d_in[10];
    const float* b_hh0   = (const float*)d_in[11];
    const float* W_ih1   = (const float*)d_in[12];
    const float* W_hh1   = (const float*)d_in[13];
    const float* b_ih1   = (const float*)d_in[14];
    const float* b_hh1   = (const float*)d_in[15];
    const float* W_outp  = (const float*)d_in[16];
    const float* b_outp  = (const float*)d_in[17];
    float* out = (float*)d_out;

    cudaFuncSetAttribute(rec_tc_kernel,
                         cudaFuncAttributeMaxDynamicSharedMemorySize, 168960);

    zero_h0_kernel<<<64, 512>>>();
    gctx_kernel<<<64, 256>>>(ecc, cat, num, ce0, ce1, ce2, W_ih0, b_ih0, b_hh0);
    ptable_kernel<<<2080, 256>>>(bemb, W_ih0);
    gx0_kernel<<<dim3(T_LEN, B_SZ), 128>>>(payload);
    convw_kernel<<<4096, 256>>>(W_ih1, 0, 2048 * 512);
    convw_kernel<<<512, 256>>>(W_outp, 1, 256 * 512);
    convwhh_kernel<<<512, 256>>>(W_hh0, 0);
    convwhh_kernel<<<512, 256>>>(W_hh1, 1);
    rec_tc_kernel<<<128, 128, 168960>>>(0);
    mma_gemm_kernel<<<dim3(16, 256), 256>>>(b_ih1, b_hh1, out, 0);
    rec_tc_kernel<<<128, 128, 168960>>>(1);
    mma_gemm_kernel<<<dim3(2, 256), 256>>>(b_outp, b_outp, out, 1);
}

// round 16
// speedup vs baseline: 1.3754x; 1.3754x over previous
#include <cuda_runtime.h>
#include <cuda_bf16.h>
#include <cuda_fp16.h>
#include <math.h>
#include <stdint.h>

// ---------------------------------------------------------------------------
// Problem constants
// ---------------------------------------------------------------------------
#define T_LEN 512
#define B_SZ  64
#define HID   512
#define G4    2048          // 4*HID (gate rows)
#define CTXD  792
#define INDIM 1048

// ---------------------------------------------------------------------------
// Device scratch
// ---------------------------------------------------------------------------
__device__ float d_gctx[B_SZ * G4];                               // [b][g]
__device__ float d_P[260 * 8 * G4];                               // [(v*8+j)][g]
__device__ float d_gx0[(size_t)T_LEN * B_SZ * G4];                // [t][b][g]
__device__ float d_gx1[(size_t)T_LEN * B_SZ * G4];                // [t][b][g]

// hidden state: bf16 hi/lo split (for the big GEMMs) and fp16 single
// (recurrence B operand), layout [t+1][b][k] (slab 0 = zeros).
__device__ __nv_bfloat16 d_h1hi[(size_t)(T_LEN + 1) * B_SZ * HID];
__device__ __nv_bfloat16 d_h1lo[(size_t)(T_LEN + 1) * B_SZ * HID];
__device__ __nv_bfloat16 d_h2hi[(size_t)(T_LEN + 1) * B_SZ * HID];
__device__ __nv_bfloat16 d_h2lo[(size_t)(T_LEN + 1) * B_SZ * HID];
__device__ __half        d_h1f16[(size_t)(T_LEN + 1) * B_SZ * HID];
__device__ __half        d_h2f16[(size_t)(T_LEN + 1) * B_SZ * HID];

// bf16-split weights for the big GEMMs
__device__ __nv_bfloat16 d_W1hi[2048 * 512], d_W1lo[2048 * 512];  // W_ih1
__device__ __nv_bfloat16 d_Wohi[256 * 512],  d_Wolo[256 * 512];   // W_out

// per-CTA tiled W_hh images for the recurrence (fp16 hi/lo split:
// A error 2^-22, so gate error is dominated by h's fp16 rounding 2^-11)
__device__ __half d_WThi[2 * 128 * 8192];
__device__ __half d_WTlo[2 * 128 * 8192];

__device__ unsigned g_cnt = 0;
__device__ volatile unsigned g_gen = 0;

// ---------------------------------------------------------------------------
// Software grid barrier for 128 co-resident CTAs (R13-proven single counter;
// tree variants were neutral-or-worse 3x)
// ---------------------------------------------------------------------------
__device__ __forceinline__ void grid_sync128() {
    __syncthreads();
    if (threadIdx.x == 0) {
        __threadfence();
        unsigned my = g_gen;                     // read BEFORE arriving
        if (atomicAdd(&g_cnt, 1u) == 127u) {
            g_cnt = 0;
            __threadfence();
            g_gen = my + 1;                      // release
        } else {
            while (g_gen == my) { }              // volatile spin (L2)
        }
    }
    __syncthreads();
}

// fast, safe pointwise helpers
__device__ __forceinline__ float sigm(float x) {
    x = fminf(fmaxf(x, -30.f), 30.f);
    return __fdividef(1.f, 1.f + __expf(-x));
}
__device__ __forceinline__ float tanh_f(float x) {
    x = fminf(fmaxf(x, -15.f), 15.f);
    float e = __expf(-2.f * x);
    return (1.f - e) * __fdividef(1.f, 1.f + e);
}

// ---------------------------------------------------------------------------
// warp-level tensor-core + cp.async helpers (base PTX ISA, compute_103-safe)
// ---------------------------------------------------------------------------
__device__ __forceinline__ uint32_t smem_u32(const void* p) {
    uint32_t a;
    asm("{ .reg .u64 t; cvta.to.shared.u64 t, %1; cvt.u32.u64 %0, t; }" : "=r"(a) : "l"(p));
    return a;
}
__device__ __forceinline__ void ldm_x4(uint32_t* r, uint32_t addr) {
    asm volatile("ldmatrix.sync.aligned.m8n8.x4.shared.b16 {%0,%1,%2,%3}, [%4];"
        : "=r"(r[0]), "=r"(r[1]), "=r"(r[2]), "=r"(r[3]) : "r"(addr));
}
__device__ __forceinline__ void hmma(float* d, const uint32_t* a, const uint32_t* b) {
    asm volatile("mma.sync.aligned.m16n8k16.row.col.f32.bf16.bf16.f32 "
        "{%0,%1,%2,%3}, {%4,%5,%6,%7}, {%8,%9}, {%0,%1,%2,%3};"
        : "+f"(d[0]), "+f"(d[1]), "+f"(d[2]), "+f"(d[3])
        : "r"(a[0]), "r"(a[1]), "r"(a[2]), "r"(a[3]), "r"(b[0]), "r"(b[1]));
}
__device__ __forceinline__ void hmma16(float* d, const uint32_t* a, const uint32_t* b) {
    asm volatile("mma.sync.aligned.m16n8k16.row.col.f32.f16.f16.f32 "
        "{%0,%1,%2,%3}, {%4,%5,%6,%7}, {%8,%9}, {%0,%1,%2,%3};"
        : "+f"(d[0]), "+f"(d[1]), "+f"(d[2]), "+f"(d[3])
        : "r"(a[0]), "r"(a[1]), "r"(a[2]), "r"(a[3]), "r"(b[0]), "r"(b[1]));
}
#define CP_ASYNC16(dst, src) \
    asm volatile("cp.async.cg.shared.global [%0], [%1], 16;" :: "r"(dst), "l"(src) : "memory")
#define CP_COMMIT() asm volatile("cp.async.commit_group;" ::: "memory")
#define CP_WAIT(N)  asm volatile("cp.async.wait_group %0;" :: "n"(N) : "memory")

// smem tile geometry: rows of 32 b16 elems (64B), 16B chunks swizzled.
__device__ __forceinline__ uint32_t swz_off(int row, int c16) {
    return (uint32_t)(row * 64 + ((c16 ^ ((row >> 1) & 3)) << 4));
}
__device__ __forceinline__ uint32_t frag_addr(uint32_t sbase, int row0, int kk, int lane) {
    int row = row0 + (lane & 7) + ((lane >> 3) & 1) * 8;
    int c16 = (kk >> 3) + (lane >> 4);
    return sbase + swz_off(row, c16);
}

// ---------------------------------------------------------------------------
// K0: zero t=0 slabs of all hidden-state buffers
// ---------------------------------------------------------------------------
__global__ void zero_h0_kernel() {
    int i = blockIdx.x * blockDim.x + threadIdx.x;
    if (i < HID * B_SZ) {
        __nv_bfloat16 z = __float2bfloat16(0.f);
        d_h1hi[i] = z; d_h1lo[i] = z; d_h2hi[i] = z; d_h2lo[i] = z;
        d_h1f16[i] = __float2half(0.f); d_h2f16[i] = __float2half(0.f);
    }
}

// ---------------------------------------------------------------------------
// K1: gctx
// ---------------------------------------------------------------------------
__global__ __launch_bounds__(256) void gctx_kernel(
    const float* __restrict__ conv, const int* __restrict__ cat,
    const float* __restrict__ num, const float* __restrict__ ce0,
    const float* __restrict__ ce1, const float* __restrict__ ce2,
    const float* __restrict__ W_ih0, const float* __restrict__ b_ih0,
    const float* __restrict__ b_hh0)
{
    __shared__ __align__(16) float ctx[CTXD];
    int b = blockIdx.x, tid = threadIdx.x;
    int i0 = cat[b * 3 + 0], i1 = cat[b * 3 + 1], i2 = cat[b * 3 + 2];
    for (int i = tid; i < 512; i += 256) ctx[i]       = conv[b * 512 + i];
    for (int i = tid; i < 50;  i += 256) ctx[512 + i] = ce0[i0 * 50 + i];
    for (int i = tid; i < 64;  i += 256) ctx[562 + i] = ce1[i1 * 64 + i];
    for (int i = tid; i < 150; i += 256) ctx[626 + i] = ce2[i2 * 150 + i];
    for (int i = tid; i < 16;  i += 256) ctx[776 + i] = num[b * 16 + i];
    __syncthreads();
    const float4* cv = (const float4*)ctx;
    for (int g = tid; g < G4; g += 256) {
        const float4* wr = (const float4*)(W_ih0 + (size_t)g * INDIM);
        float acc = b_ih0[g] + b_hh0[g];
        #pragma unroll 4
        for (int kk = 0; kk < 198; ++kk) {
            float4 w = wr[kk], c4 = cv[kk];
            acc = fmaf(w.x, c4.x, fmaf(w.y, c4.y, fmaf(w.z, c4.z, fmaf(w.w, c4.w, acc))));
        }
        d_gctx[b * G4 + g] = acc;
    }
}

// ---------------------------------------------------------------------------
// K2: byte projection table
// ---------------------------------------------------------------------------
__global__ __launch_bounds__(256) void ptable_kernel(
    const float* __restrict__ byte_emb, const float* __restrict__ W_ih0)
{
    int pid = blockIdx.x;
    int v = pid >> 3, j = pid & 7;
    __shared__ float e[32];
    if (threadIdx.x < 32) e[threadIdx.x] = byte_emb[v * 32 + threadIdx.x];
    __syncthreads();
    for (int g = threadIdx.x; g < G4; g += 256) {
        const float* wr = W_ih0 + (size_t)g * INDIM + CTXD + j * 32;
        float acc = 0.f;
        #pragma unroll
        for (int d = 0; d < 32; ++d) acc = fmaf(e[d], wr[d], acc);
        d_P[(size_t)pid * G4 + g] = acc;
    }
}

// ---------------------------------------------------------------------------
// K3: gx0 assembly via gathers
// ---------------------------------------------------------------------------
__global__ __launch_bounds__(128) void gx0_kernel(const int* __restrict__ payload)
{
    int t = blockIdx.x, b = blockIdx.y, tid = threadIdx.x;
    __shared__ int rows[8];
    if (tid < 8) {
        int q = t + tid;
        int v = (q < 7) ? 256 : ((q == 7) ? 257 : payload[b * 512 + (q - 8)]);
        rows[tid] = v * 8 + tid;
    }
    __syncthreads();
    float4* outp = (float4*)(d_gx0 + ((size_t)t * B_SZ + b) * G4);
    const float4* gc = (const float4*)(d_gctx + b * G4);
    #pragma unroll
    for (int p = 0; p < 4; ++p) {
        int g4 = p * 128 + tid;
        float4 acc = gc[g4];
        #pragma unroll
        for (int j = 0; j < 8; ++j) {
            float4 pv = ((const float4*)(d_P + (size_t)rows[j] * G4))[g4];
            acc.x += pv.x; acc.y += pv.y; acc.z += pv.z; acc.w += pv.w;
        }
        outp[g4] = acc;
    }
}

// ---------------------------------------------------------------------------
// KW: fp32 weights -> bf16 hi/lo split. which: 0=W_ih1, 1=W_out.
// ---------------------------------------------------------------------------
__global__ __launch_bounds__(256) void convw_kernel(
    const float* __restrict__ W, int which, int n)
{
    __nv_bfloat16* hi = which ? d_Wohi : d_W1hi;
    __nv_bfloat16* lo = which ? d_Wolo : d_W1lo;
    int i = blockIdx.x * 256 + threadIdx.x;
    if (i < n) {
        float x = W[i];
        __nv_bfloat16 h = __float2bfloat16(x);
        hi[i] = h;
        lo[i] = __float2bfloat16(x - __bfloat162float(h));
    }
}

// ---------------------------------------------------------------------------
// KWT: W_hh -> per-CTA tiled fp16 hi/lo images for rec_tc.
// ---------------------------------------------------------------------------
__global__ __launch_bounds__(256) void convwhh_kernel(
    const float* __restrict__ Whh, int layer)
{
    int idx = blockIdx.x * 256 + threadIdx.x;    // [0, 131072)
    int c = idx >> 10, rem = idx & 1023;
    int r = rem >> 6, rem2 = rem & 63;
    int ch = rem2 >> 2, c16 = rem2 & 3;
    int g = r >> 2, u = r & 3;
    const float* src = Whh + ((size_t)(g * 512 + c * 4 + u)) * 512 + ch * 32 + c16 * 8;
    float4 v0 = *(const float4*)src;
    float4 v1 = *(const float4*)(src + 4);
    float x[8] = {v0.x, v0.y, v0.z, v0.w, v1.x, v1.y, v1.z, v1.w};
    ushort hs[8], ls[8];
    #pragma unroll
    for (int i = 0; i < 8; ++i) {
        __half h = __float2half(x[i]);
        __half l = __float2half(x[i] - __half2float(h));
        hs[i] = __half_as_ushort(h);
        ls[i] = __half_as_ushort(l);
    }
    size_t dst = ((size_t)layer * 128 + c) * 16384 + ch * 1024 + swz_off(r, c16);
    uint4 ph, pl;
    ph.x = hs[0] | ((uint32_t)hs[1] << 16); ph.y = hs[2] | ((uint32_t)hs[3] << 16);
    ph.z = hs[4] | ((uint32_t)hs[5] << 16); ph.w = hs[6] | ((uint32_t)hs[7] << 16);
    pl.x = ls[0] | ((uint32_t)ls[1] << 16); pl.y = ls[2] | ((uint32_t)ls[3] << 16);
    pl.z = ls[4] | ((uint32_t)ls[5] << 16); pl.w = ls[6] | ((uint32_t)ls[7] << 16);
    *(uint4*)((uint8_t*)d_WThi + dst) = ph;
    *(uint4*)((uint8_t*)d_WTlo + dst) = pl;
}

// ---------------------------------------------------------------------------
// K4/K6: tensor-core persistent LSTM recurrence (R13 structure, fp16 2-term).
// 128 CTAs x 128 threads, 96KB smem. A = W split fp16 hi/lo (stationary);
// B = h[t] as SINGLE fp16 tile (64KB streamed, was 128KB for bf16 hi+lo);
// per kk: 3 ldmatrix + 4 HMMA (was 4 + 6). h[t+1] stored as fp16 (next rec
// step) AND bf16 hi/lo (mma_gemm consumption).
// ---------------------------------------------------------------------------
__global__ __launch_bounds__(128, 1) void rec_tc_kernel(int layer)
{
    extern __shared__ __align__(16) uint8_t sm[];
    uint8_t* sAh = sm;                 // 16 KB
    uint8_t* sAl = sm + 16384;         // 16 KB
    uint8_t* sB  = sm + 32768;         // 64 KB: [16 ch][64 b][64B]

    const float* gx = layer ? d_gx1 : d_gx0;
    __nv_bfloat16* hhi = layer ? d_h2hi : d_h1hi;
    __nv_bfloat16* hlo = layer ? d_h2lo : d_h1lo;
    __half*        hf  = layer ? d_h2f16 : d_h1f16;

    int tid = threadIdx.x, lane = tid & 31, w = tid >> 5;
    int blk = blockIdx.x;

    // stationary A tiles (already tile-formatted by convwhh)
    {
        const uint4* srcH = (const uint4*)(d_WThi + ((size_t)layer * 128 + blk) * 8192);
        const uint4* srcL = (const uint4*)(d_WTlo + ((size_t)layer * 128 + blk) * 8192);
        for (int i = tid; i < 1024; i += 128) {
            ((uint4*)sAh)[i] = srcH[i];
            ((uint4*)sAl)[i] = srcL[i];
        }
    }

    uint32_t bAh = smem_u32(sAh), bAl = smem_u32(sAl), bB = smem_u32(sB);

    int r = lane >> 2;                 // D row group (0..7)
    int cp = lane & 3;                 // batch pair within n-tile
    bool pw = (r < 4);                 // pointwise-owning lanes (i,g rows)
    int uglob = blk * 4 + r;           // this lane's unit (when pw)

    float cst[2][2] = {};              // cell state [nt][batch 0/1]

    for (int t = 0; t < T_LEN; ++t) {
        grid_sync128();                // h[t] fully published by all CTAs
        const uint8_t* srcF = (const uint8_t*)hf + (size_t)t * 65536;

        // prefetch gate inputs (scattered, DRAM; consumed only in pointwise
        // at loop end so latency fully hides — R15 showed staging these
        // through smem in front of the MMA regresses)
        float q[2][4][2];
        if (pw) {
            #pragma unroll
            for (int nt = 0; nt < 2; ++nt) {
                int b0 = w * 16 + nt * 8 + cp * 2;
                const float* g0 = gx + ((size_t)t * B_SZ + b0) * G4 + uglob;
                #pragma unroll
                for (int g = 0; g < 4; ++g) {
                    q[nt][g][0] = g0[g * 512];
                    q[nt][g][1] = g0[g * 512 + G4];
                }
            }
        }

        // issue B-tile cp.asyncs in 4 quarter-groups (chunks 4q..4q+4)
        #pragma unroll
        for (int qq = 0; qq < 4; ++qq) {
            #pragma unroll
            for (int i = 0; i < 8; ++i) {
                int idx = tid + i * 128;                 // [0,1024)
                int b = idx >> 4, chl = (idx >> 2) & 3, c16 = idx & 3;
                int ch = qq * 4 + chl;
                uint32_t so = (uint32_t)(b * 1024 + ch * 64 + c16 * 16);
                uint32_t dofs = ch * 4096 + swz_off(b, c16);
                CP_ASYNC16(bB + dofs, srcF + so);
            }
            CP_COMMIT();
        }

        float acc[2][4] = {};

        // MMA quarters, overlapped with the remaining cp.async streams
        #pragma unroll
        for (int qq = 0; qq < 4; ++qq) {
            if (qq == 0) CP_WAIT(3);
            else if (qq == 1) CP_WAIT(2);
            else if (qq == 2) CP_WAIT(1);
            else CP_WAIT(0);
            __syncthreads();
            #pragma unroll
            for (int chl = 0; chl < 4; ++chl) {
                int ch = qq * 4 + chl;
                #pragma unroll
                for (int kk = 0; kk < 32; kk += 16) {
                    uint32_t aH[4], aL[4], rr[4];
                    ldm_x4(aH, frag_addr(bAh + ch * 1024, 0, kk, lane));
                    ldm_x4(aL, frag_addr(bAl + ch * 1024, 0, kk, lane));
                    uint32_t bF[2][2];
                    ldm_x4(rr, frag_addr(bB + ch * 4096, w * 16, kk, lane));
                    bF[0][0] = rr[0]; bF[0][1] = rr[2];
                    bF[1][0] = rr[1]; bF[1][1] = rr[3];
                    #pragma unroll
                    for (int nt = 0; nt < 2; ++nt) {
                        hmma16(acc[nt], aH, bF[nt]);
                        hmma16(acc[nt], aL, bF[nt]);
                    }
                }
            }
        }
        __syncthreads();   // B tile free for next step's cp.async after this

        // pointwise: lanes<16 have i (acc[nt][0..1]) and g (acc[nt][2..3]);
        // partner lane+16 has f and o for the same unit/batches.
        #pragma unroll
        for (int nt = 0; nt < 2; ++nt) {
            float f0 = __shfl_xor_sync(0xffffffffu, acc[nt][0], 16);
            float f1 = __shfl_xor_sync(0xffffffffu, acc[nt][1], 16);
            float o0 = __shfl_xor_sync(0xffffffffu, acc[nt][2], 16);
            float o1 = __shfl_xor_sync(0xffffffffu, acc[nt][3], 16);
            if (pw) {
                float gi0 = acc[nt][0] + q[nt][0][0];
                float gf0 = f0          + q[nt][1][0];
                float gg0 = acc[nt][2] + q[nt][2][0];
                float go0 = o0          + q[nt][3][0];
                float gi1 = acc[nt][1] + q[nt][0][1];
                float gf1 = f1          + q[nt][1][1];
                float gg1 = acc[nt][3] + q[nt][2][1];
                float go1 = o1          + q[nt][3][1];
                cst[nt][0] = fmaf(sigm(gf0), cst[nt][0], sigm(gi0) * tanh_f(gg0));
                cst[nt][1] = fmaf(sigm(gf1), cst[nt][1], sigm(gi1) * tanh_f(gg1));
                float h0 = sigm(go0) * tanh_f(cst[nt][0]);
                float h1 = sigm(go1) * tanh_f(cst[nt][1]);
                int b0 = w * 16 + nt * 8 + cp * 2;
                size_t base = (size_t)(t + 1) * 32768 + (size_t)b0 * 512 + uglob;
                __nv_bfloat16 hh0 = __float2bfloat16(h0);
                __nv_bfloat16 hh1 = __float2bfloat16(h1);
                hhi[base]       = hh0;
                hlo[base]       = __float2bfloat16(h0 - __bfloat162float(hh0));
                hhi[base + 512] = hh1;
                hlo[base + 512] = __float2bfloat16(h1 - __bfloat162float(hh1));
                hf[base]        = __float2half(h0);
                hf[base + 512]  = __float2half(h1);
            }
        }
    }
}

// ---------------------------------------------------------------------------
// KG: warp-tiled bf16-split mma.sync GEMM (R12-proven, unchanged).
// mode 0: A=h1, B=W_ih1, out = d_gx1 + bias1+bias2
// mode 1: A=h2, B=W_out, out = outp  + bias1
// ---------------------------------------------------------------------------
__global__ __launch_bounds__(256) void mma_gemm_kernel(
    const float* __restrict__ bias1, const float* __restrict__ bias2,
    float* __restrict__ outp, int mode)
{
    __shared__ __align__(16) uint8_t sAh[8192], sAl[8192], sBh[8192], sBl[8192];

    int tid = threadIdx.x, lane = tid & 31, wid = tid >> 5;
    int mw = wid & 3, nw = wid >> 2;
    int n0 = blockIdx.x * 128, tp = blockIdx.y;

    uint32_t bAh = smem_u32(sAh), bAl = smem_u32(sAl);
    uint32_t bBh = smem_u32(sBh), bBl = smem_u32(sBl);

    const __nv_bfloat16* Ah = (mode ? d_h2hi : d_h1hi) + (size_t)(2 * tp + 1) * 32768;
    const __nv_bfloat16* Al = (mode ? d_h2lo : d_h1lo) + (size_t)(2 * tp + 1) * 32768;
    const __nv_bfloat16* Bh = (mode ? d_Wohi : d_W1hi) + (size_t)n0 * 512;
    const __nv_bfloat16* Bl = (mode ? d_Wolo : d_W1lo) + (size_t)n0 * 512;

    float acc[2][8][4] = {};

    int r0t = tid >> 2,          c0t = tid & 3;
    int r1t = (tid + 256) >> 2,  c1t = tid & 3;
    uint32_t d0 = swz_off(r0t, c0t), d1 = swz_off(r1t, c1t);

    for (int kc = 0; kc < 512; kc += 32) {
        uint4 vah0 = *(const uint4*)(Ah + (size_t)r0t * 512 + kc + c0t * 8);
        uint4 vah1 = *(const uint4*)(Ah + (size_t)r1t * 512 + kc + c1t * 8);
        uint4 val0 = *(const uint4*)(Al + (size_t)r0t * 512 + kc + c0t * 8);
        uint4 val1 = *(const uint4*)(Al + (size_t)r1t * 512 + kc + c1t * 8);
        uint4 vbh0 = *(const uint4*)(Bh + (size_t)r0t * 512 + kc + c0t * 8);
        uint4 vbh1 = *(const uint4*)(Bh + (size_t)r1t * 512 + kc + c1t * 8);
        uint4 vbl0 = *(const uint4*)(Bl + (size_t)r0t * 512 + kc + c0t * 8);
        uint4 vbl1 = *(const uint4*)(Bl + (size_t)r1t * 512 + kc + c1t * 8);

        __syncthreads();
        *(uint4*)(sAh + d0) = vah0;  *(uint4*)(sAh + d1) = vah1;
        *(uint4*)(sAl + d0) = val0;  *(uint4*)(sAl + d1) = val1;
        *(uint4*)(sBh + d0) = vbh0;  *(uint4*)(sBh + d1) = vbh1;
        *(uint4*)(sBl + d0) = vbl0;  *(uint4*)(sBl + d1) = vbl1;
        __syncthreads();

        #pragma unroll
        for (int kk = 0; kk < 32; kk += 16) {
            uint32_t aH[2][4], aL[2][4], bb[8][2];
            #pragma unroll
            for (int mt = 0; mt < 2; ++mt) {
                ldm_x4(aH[mt], frag_addr(bAh, mw * 32 + mt * 16, kk, lane));
                ldm_x4(aL[mt], frag_addr(bAl, mw * 32 + mt * 16, kk, lane));
            }
            #pragma unroll
            for (int q = 0; q < 4; ++q) {
                uint32_t rr[4];
                ldm_x4(rr, frag_addr(bBh, nw * 64 + q * 16, kk, lane));
                bb[2 * q][0] = rr[0]; bb[2 * q][1] = rr[2];
                bb[2 * q + 1][0] = rr[1]; bb[2 * q + 1][1] = rr[3];
            }
            #pragma unroll
            for (int mt = 0; mt < 2; ++mt)
                #pragma unroll
                for (int nt = 0; nt < 8; ++nt) {
                    hmma(acc[mt][nt], aH[mt], bb[nt]);
                    hmma(acc[mt][nt], aL[mt], bb[nt]);
                }
            #pragma unroll
            for (int q = 0; q < 4; ++q) {
                uint32_t rr[4];
                ldm_x4(rr, frag_addr(bBl, nw * 64 + q * 16, kk, lane));
                bb[2 * q][0] = rr[0]; bb[2 * q][1] = rr[2];
                bb[2 * q + 1][0] = rr[1]; bb[2 * q + 1][1] = rr[3];
            }
            #pragma unroll
            for (int mt = 0; mt < 2; ++mt)
                #pragma unroll
                for (int nt = 0; nt < 8; ++nt)
                    hmma(acc[mt][nt], aH[mt], bb[nt]);
        }
    }

    int gr = lane >> 2, gc2 = (lane & 3) * 2;
    #pragma unroll
    for (int mt = 0; mt < 2; ++mt) {
        #pragma unroll
        for (int half = 0; half < 2; ++half) {
            int row = mw * 32 + mt * 16 + gr + half * 8;
            int t = tp * 2 + (row >> 6), b = row & 63;
            #pragma unroll
            for (int nt = 0; nt < 8; ++nt) {
                int col = n0 + nw * 64 + nt * 8 + gc2;
                float z0 = bias1[col], z1 = bias1[col + 1];
                if (mode == 0) { z0 += bias2[col]; z1 += bias2[col + 1]; }
                float2 st = make_float2(acc[mt][nt][half * 2 + 0] + z0,
                                        acc[mt][nt][half * 2 + 1] + z1);
                if (mode == 0)
                    *(float2*)(d_gx1 + ((size_t)t * B_SZ + b) * G4 + col) = st;
                else
                    *(float2*)(outp + ((size_t)b * T_LEN + t) * 256 + col) = st;
            }
        }
    }
}

// ---------------------------------------------------------------------------
// kernel_launch
// ---------------------------------------------------------------------------
extern "C" void kernel_launch(void* const* d_in, const int* in_sizes, int n_in,
                              void* d_out, int out_size) {
    const float* ecc     = (const float*)d_in[0];
    const int*   cat     = (const int*)  d_in[1];
    const float* num     = (const float*)d_in[2];
    const int*   payload = (const int*)  d_in[3];
    const float* ce0     = (const float*)d_in[4];
    const float* ce1     = (const float*)d_in[5];
    const float* ce2     = (const float*)d_in[6];
    const float* bemb    = (const float*)d_in[7];
    const float* W_ih0   = (const float*)d_in[8];
    const float* W_hh0   = (const float*)d_in[9];
    const float* b_ih0   = (const float*)d_in[10];
    const float* b_hh0   = (const float*)d_in[11];
    const float* W_ih1   = (const float*)d_in[12];
    const float* W_hh1   = (const float*)d_in[13];
    const float* b_ih1   = (const float*)d_in[14];
    const float* b_hh1   = (const float*)d_in[15];
    const float* W_outp  = (const float*)d_in[16];
    const float* b_outp  = (const float*)d_in[17];
    float* out = (float*)d_out;

    cudaFuncSetAttribute(rec_tc_kernel,
                         cudaFuncAttributeMaxDynamicSharedMemorySize, 98304);

    zero_h0_kernel<<<64, 512>>>();
    gctx_kernel<<<64, 256>>>(ecc, cat, num, ce0, ce1, ce2, W_ih0, b_ih0, b_hh0);
    ptable_kernel<<<2080, 256>>>(bemb, W_ih0);
    gx0_kernel<<<dim3(T_LEN, B_SZ), 128>>>(payload);
    convw_kernel<<<4096, 256>>>(W_ih1, 0, 2048 * 512);
    convw_kernel<<<512, 256>>>(W_outp, 1, 256 * 512);
    convwhh_kernel<<<512, 256>>>(W_hh0, 0);
    convwhh_kernel<<<512, 256>>>(W_hh1, 1);
    rec_tc_kernel<<<128, 128, 98304>>>(0);
    mma_gemm_kernel<<<dim3(16, 256), 256>>>(b_ih1, b_hh1, out, 0);
    rec_tc_kernel<<<128, 128, 98304>>>(1);
    mma_gemm_kernel<<<dim3(2, 256), 256>>>(b_outp, b_outp, out, 1);
}

// round 17
// speedup vs baseline: 1.9183x; 1.3947x over previous
#include <cuda_runtime.h>
#include <cuda_bf16.h>
#include <cuda_fp16.h>
#include <math.h>
#include <stdint.h>

// ---------------------------------------------------------------------------
// Problem constants
// ---------------------------------------------------------------------------
#define T_LEN 512
#define B_SZ  64
#define HID   512
#define G4    2048          // 4*HID (gate rows)
#define CTXD  792
#define INDIM 1048
#define SLABB 65536         // bytes per h slab (64*512 fp16)

// ---------------------------------------------------------------------------
// Device scratch
// ---------------------------------------------------------------------------
__device__ float d_gctx[B_SZ * G4];                               // [b][g]
__device__ float d_P[260 * 8 * G4];                               // [(v*8+j)][g]
__device__ float d_gx0[(size_t)T_LEN * B_SZ * G4];                // [t][b][g]

// hidden state, layout [t+1][b][k] (slab 0 = zeros).
// h1: fp16 only (consumed by the fused kernel's layer-1 input GEMM).
// h2: fp16 (recurrence) + bf16 hi/lo (logits GEMM).
__device__ __half        d_h1f16[(size_t)(T_LEN + 1) * B_SZ * HID];
__device__ __half        d_h2f16[(size_t)(T_LEN + 1) * B_SZ * HID];
__device__ __nv_bfloat16 d_h2hi[(size_t)(T_LEN + 1) * B_SZ * HID];
__device__ __nv_bfloat16 d_h2lo[(size_t)(T_LEN + 1) * B_SZ * HID];

// bf16-split weights for the logits GEMM
__device__ __nv_bfloat16 d_Wohi[256 * 512], d_Wolo[256 * 512];

// per-CTA tiled weight images for the fused recurrence:
// 32 rows x 512 k per (layer, sub) tile (32KB each).
// hh: fp16 hi/lo split (recurrent path, error 2^-22);
// ih: W_ih1 single fp16 (feedforward, one-shot 2^-11 — same order as h fp16).
__device__ __half d_WThh_hi[2 * 64 * 16384];
__device__ __half d_WThh_lo[2 * 64 * 16384];
__device__ __half d_WTih[64 * 16384];

__device__ unsigned g_cnt = 0;
__device__ volatile unsigned g_gen = 0;

// ---------------------------------------------------------------------------
// Software grid barrier for 128 co-resident CTAs (proven single counter)
// ---------------------------------------------------------------------------
__device__ __forceinline__ void grid_sync128() {
    __syncthreads();
    if (threadIdx.x == 0) {
        __threadfence();
        unsigned my = g_gen;                     // read BEFORE arriving
        if (atomicAdd(&g_cnt, 1u) == 127u) {
            g_cnt = 0;
            __threadfence();
            g_gen = my + 1;                      // release
        } else {
            while (g_gen == my) { }              // volatile spin (L2)
        }
    }
    __syncthreads();
}

// fast, safe pointwise helpers
__device__ __forceinline__ float sigm(float x) {
    x = fminf(fmaxf(x, -30.f), 30.f);
    return __fdividef(1.f, 1.f + __expf(-x));
}
__device__ __forceinline__ float tanh_f(float x) {
    x = fminf(fmaxf(x, -15.f), 15.f);
    float e = __expf(-2.f * x);
    return (1.f - e) * __fdividef(1.f, 1.f + e);
}

// ---------------------------------------------------------------------------
// warp-level tensor-core + cp.async helpers (base PTX ISA, compute_103-safe)
// ---------------------------------------------------------------------------
__device__ __forceinline__ uint32_t smem_u32(const void* p) {
    uint32_t a;
    asm("{ .reg .u64 t; cvta.to.shared.u64 t, %1; cvt.u32.u64 %0, t; }" : "=r"(a) : "l"(p));
    return a;
}
__device__ __forceinline__ void ldm_x4(uint32_t* r, uint32_t addr) {
    asm volatile("ldmatrix.sync.aligned.m8n8.x4.shared.b16 {%0,%1,%2,%3}, [%4];"
        : "=r"(r[0]), "=r"(r[1]), "=r"(r[2]), "=r"(r[3]) : "r"(addr));
}
__device__ __forceinline__ void hmma(float* d, const uint32_t* a, const uint32_t* b) {
    asm volatile("mma.sync.aligned.m16n8k16.row.col.f32.bf16.bf16.f32 "
        "{%0,%1,%2,%3}, {%4,%5,%6,%7}, {%8,%9}, {%0,%1,%2,%3};"
        : "+f"(d[0]), "+f"(d[1]), "+f"(d[2]), "+f"(d[3])
        : "r"(a[0]), "r"(a[1]), "r"(a[2]), "r"(a[3]), "r"(b[0]), "r"(b[1]));
}
__device__ __forceinline__ void hmma16(float* d, const uint32_t* a, const uint32_t* b) {
    asm volatile("mma.sync.aligned.m16n8k16.row.col.f32.f16.f16.f32 "
        "{%0,%1,%2,%3}, {%4,%5,%6,%7}, {%8,%9}, {%0,%1,%2,%3};"
        : "+f"(d[0]), "+f"(d[1]), "+f"(d[2]), "+f"(d[3])
        : "r"(a[0]), "r"(a[1]), "r"(a[2]), "r"(a[3]), "r"(b[0]), "r"(b[1]));
}
#define CP_ASYNC16(dst, src) \
    asm volatile("cp.async.cg.shared.global [%0], [%1], 16;" :: "r"(dst), "l"(src) : "memory")
#define CP_COMMIT() asm volatile("cp.async.commit_group;" ::: "memory")
#define CP_WAIT(N)  asm volatile("cp.async.wait_group %0;" :: "n"(N) : "memory")

// smem tile geometry: rows of 32 b16 elems (64B), 16B chunks swizzled.
__device__ __forceinline__ uint32_t swz_off(int row, int c16) {
    return (uint32_t)(row * 64 + ((c16 ^ ((row >> 1) & 3)) << 4));
}
__device__ __forceinline__ uint32_t frag_addr(uint32_t sbase, int row0, int kk, int lane) {
    int row = row0 + (lane & 7) + ((lane >> 3) & 1) * 8;
    int c16 = (kk >> 3) + (lane >> 4);
    return sbase + swz_off(row, c16);
}

// ---------------------------------------------------------------------------
// K0: zero t=0 slabs of all hidden-state buffers
// ---------------------------------------------------------------------------
__global__ void zero_h0_kernel() {
    int i = blockIdx.x * blockDim.x + threadIdx.x;
    if (i < HID * B_SZ) {
        d_h1f16[i] = __float2half(0.f);
        d_h2f16[i] = __float2half(0.f);
        __nv_bfloat16 z = __float2bfloat16(0.f);
        d_h2hi[i] = z; d_h2lo[i] = z;
    }
}

// ---------------------------------------------------------------------------
// K1: gctx
// ---------------------------------------------------------------------------
__global__ __launch_bounds__(256) void gctx_kernel(
    const float* __restrict__ conv, const int* __restrict__ cat,
    const float* __restrict__ num, const float* __restrict__ ce0,
    const float* __restrict__ ce1, const float* __restrict__ ce2,
    const float* __restrict__ W_ih0, const float* __restrict__ b_ih0,
    const float* __restrict__ b_hh0)
{
    __shared__ __align__(16) float ctx[CTXD];
    int b = blockIdx.x, tid = threadIdx.x;
    int i0 = cat[b * 3 + 0], i1 = cat[b * 3 + 1], i2 = cat[b * 3 + 2];
    for (int i = tid; i < 512; i += 256) ctx[i]       = conv[b * 512 + i];
    for (int i = tid; i < 50;  i += 256) ctx[512 + i] = ce0[i0 * 50 + i];
    for (int i = tid; i < 64;  i += 256) ctx[562 + i] = ce1[i1 * 64 + i];
    for (int i = tid; i < 150; i += 256) ctx[626 + i] = ce2[i2 * 150 + i];
    for (int i = tid; i < 16;  i += 256) ctx[776 + i] = num[b * 16 + i];
    __syncthreads();
    const float4* cv = (const float4*)ctx;
    for (int g = tid; g < G4; g += 256) {
        const float4* wr = (const float4*)(W_ih0 + (size_t)g * INDIM);
        float acc = b_ih0[g] + b_hh0[g];
        #pragma unroll 4
        for (int kk = 0; kk < 198; ++kk) {
            float4 w = wr[kk], c4 = cv[kk];
            acc = fmaf(w.x, c4.x, fmaf(w.y, c4.y, fmaf(w.z, c4.z, fmaf(w.w, c4.w, acc))));
        }
        d_gctx[b * G4 + g] = acc;
    }
}

// ---------------------------------------------------------------------------
// K2: byte projection table
// ---------------------------------------------------------------------------
__global__ __launch_bounds__(256) void ptable_kernel(
    const float* __restrict__ byte_emb, const float* __restrict__ W_ih0)
{
    int pid = blockIdx.x;
    int v = pid >> 3, j = pid & 7;
    __shared__ float e[32];
    if (threadIdx.x < 32) e[threadIdx.x] = byte_emb[v * 32 + threadIdx.x];
    __syncthreads();
    for (int g = threadIdx.x; g < G4; g += 256) {
        const float* wr = W_ih0 + (size_t)g * INDIM + CTXD + j * 32;
        float acc = 0.f;
        #pragma unroll
        for (int d = 0; d < 32; ++d) acc = fmaf(e[d], wr[d], acc);
        d_P[(size_t)pid * G4 + g] = acc;
    }
}

// ---------------------------------------------------------------------------
// K3: gx0 assembly via gathers
// ---------------------------------------------------------------------------
__global__ __launch_bounds__(128) void gx0_kernel(const int* __restrict__ payload)
{
    int t = blockIdx.x, b = blockIdx.y, tid = threadIdx.x;
    __shared__ int rows[8];
    if (tid < 8) {
        int q = t + tid;
        int v = (q < 7) ? 256 : ((q == 7) ? 257 : payload[b * 512 + (q - 8)]);
        rows[tid] = v * 8 + tid;
    }
    __syncthreads();
    float4* outp = (float4*)(d_gx0 + ((size_t)t * B_SZ + b) * G4);
    const float4* gc = (const float4*)(d_gctx + b * G4);
    #pragma unroll
    for (int p = 0; p < 4; ++p) {
        int g4 = p * 128 + tid;
        float4 acc = gc[g4];
        #pragma unroll
        for (int j = 0; j < 8; ++j) {
            float4 pv = ((const float4*)(d_P + (size_t)rows[j] * G4))[g4];
            acc.x += pv.x; acc.y += pv.y; acc.z += pv.z; acc.w += pv.w;
        }
        outp[g4] = acc;
    }
}

// ---------------------------------------------------------------------------
// KW: W_out -> bf16 hi/lo split (logits GEMM).
// ---------------------------------------------------------------------------
__global__ __launch_bounds__(256) void convw_out_kernel(const float* __restrict__ W)
{
    int i = blockIdx.x * 256 + threadIdx.x;
    if (i < 256 * 512) {
        float x = W[i];
        __nv_bfloat16 h = __float2bfloat16(x);
        d_Wohi[i] = h;
        d_Wolo[i] = __float2bfloat16(x - __bfloat162float(h));
    }
}

// ---------------------------------------------------------------------------
// KWT: W_hh -> per-sub tiled fp16 hi/lo images (32 rows x 512 k, swizzled).
// Tile row r: mt = r>>4, gate = (r>>2)&3, ul = r&3; unit = sub*8 + mt*4 + ul.
// ---------------------------------------------------------------------------
__global__ __launch_bounds__(256) void convwhh_kernel(
    const float* __restrict__ Whh, int layer)
{
    int idx = blockIdx.x * 256 + threadIdx.x;    // [0, 131072)
    int sub = idx >> 11, rem = idx & 2047;
    int r = rem >> 6, kg = rem & 63;
    int ch = kg >> 2, c16 = kg & 3;
    int mt = r >> 4, gate = (r >> 2) & 3, ul = r & 3;
    const float* src = Whh + ((size_t)(gate * 512 + sub * 8 + mt * 4 + ul)) * 512
                           + ch * 32 + c16 * 8;
    float4 v0 = *(const float4*)src;
    float4 v1 = *(const float4*)(src + 4);
    float x[8] = {v0.x, v0.y, v0.z, v0.w, v1.x, v1.y, v1.z, v1.w};
    ushort hs[8], ls[8];
    #pragma unroll
    for (int i = 0; i < 8; ++i) {
        __half h = __float2half(x[i]);
        __half l = __float2half(x[i] - __half2float(h));
        hs[i] = __half_as_ushort(h);
        ls[i] = __half_as_ushort(l);
    }
    size_t dst = ((size_t)(layer * 64 + sub)) * 32768 + ch * 2048 + swz_off(r, c16);
    uint4 ph, pl;
    ph.x = hs[0] | ((uint32_t)hs[1] << 16); ph.y = hs[2] | ((uint32_t)hs[3] << 16);
    ph.z = hs[4] | ((uint32_t)hs[5] << 16); ph.w = hs[6] | ((uint32_t)hs[7] << 16);
    pl.x = ls[0] | ((uint32_t)ls[1] << 16); pl.y = ls[2] | ((uint32_t)ls[3] << 16);
    pl.z = ls[4] | ((uint32_t)ls[5] << 16); pl.w = ls[6] | ((uint32_t)ls[7] << 16);
    *(uint4*)((uint8_t*)d_WThh_hi + dst) = ph;
    *(uint4*)((uint8_t*)d_WThh_lo + dst) = pl;
}

// KWI: W_ih1 -> per-sub tiled single-fp16 images (same geometry).
__global__ __launch_bounds__(256) void convwih_kernel(const float* __restrict__ Wih)
{
    int idx = blockIdx.x * 256 + threadIdx.x;    // [0, 131072)
    int sub = idx >> 11, rem = idx & 2047;
    int r = rem >> 6, kg = rem & 63;
    int ch = kg >> 2, c16 = kg & 3;
    int mt = r >> 4, gate = (r >> 2) & 3, ul = r & 3;
    const float* src = Wih + ((size_t)(gate * 512 + sub * 8 + mt * 4 + ul)) * 512
                           + ch * 32 + c16 * 8;
    float4 v0 = *(const float4*)src;
    float4 v1 = *(const float4*)(src + 4);
    float x[8] = {v0.x, v0.y, v0.z, v0.w, v1.x, v1.y, v1.z, v1.w};
    ushort hs[8];
    #pragma unroll
    for (int i = 0; i < 8; ++i) hs[i] = __half_as_ushort(__float2half(x[i]));
    size_t dst = (size_t)sub * 32768 + ch * 2048 + swz_off(r, c16);
    uint4 ph;
    ph.x = hs[0] | ((uint32_t)hs[1] << 16); ph.y = hs[2] | ((uint32_t)hs[3] << 16);
    ph.z = hs[4] | ((uint32_t)hs[5] << 16); ph.w = hs[6] | ((uint32_t)hs[7] << 16);
    *(uint4*)((uint8_t*)d_WTih + dst) = ph;
}

// ---------------------------------------------------------------------------
// K4: FUSED two-layer pipelined tensor-core LSTM.
// 128 CTAs x 128 threads, 224KB smem, 1/SM. CTAs 0-63 = layer 0 (8 units),
// CTAs 64-127 = layer 1 (8 units; computes W_ih1.h1[t] + W_hh1.h2[t-1]).
// 513 barrier generations with 1-step skew between layers — halves the
// serial step count AND deletes the separate gx1 GEMM.
// D = 32 rows (2 m-tiles, gate-major: r = mt*16 + gate*4 + ul) x 64 batch.
// ---------------------------------------------------------------------------
__global__ __launch_bounds__(128, 1) void rec_fused_kernel(
    const float* __restrict__ b_ih1, const float* __restrict__ b_hh1)
{
    extern __shared__ __align__(16) uint8_t sm[];
    uint8_t* sAh = sm;                 // hh hi   32 KB [16 ch][2KB]
    uint8_t* sAl = sm + 32768;         // hh lo   32 KB
    uint8_t* sAi = sm + 65536;         // ih      32 KB (layer1)
    uint8_t* sB1 = sm + 98304;         // h1 tile 64 KB [16 ch][4KB]
    uint8_t* sB2 = sm + 163840;        // h2 tile 64 KB (layer1)

    int tid = threadIdx.x, lane = tid & 31, w = tid >> 5;
    int blk = blockIdx.x, lay = blk >> 6, sub = blk & 63;

    // stationary A tiles
    {
        const uint4* hH = (const uint4*)((const uint8_t*)d_WThh_hi + (size_t)(lay * 64 + sub) * 32768);
        const uint4* hL = (const uint4*)((const uint8_t*)d_WThh_lo + (size_t)(lay * 64 + sub) * 32768);
        for (int i = tid; i < 2048; i += 128) {
            ((uint4*)sAh)[i] = hH[i];
            ((uint4*)sAl)[i] = hL[i];
        }
        if (lay == 1) {
            const uint4* hI = (const uint4*)((const uint8_t*)d_WTih + (size_t)sub * 32768);
            for (int i = tid; i < 2048; i += 128) ((uint4*)sAi)[i] = hI[i];
        }
    }

    uint32_t bAh = smem_u32(sAh), bAl = smem_u32(sAl), bAi = smem_u32(sAi);
    uint32_t bB1 = smem_u32(sB1), bB2 = smem_u32(sB2);

    int r = lane >> 2;                 // D row group (0..7)
    int cp = lane & 3;                 // batch pair within n-tile
    bool pw = (r < 4);                 // pointwise-owning lanes (i,g rows)

    float cst[2][2][2] = {};           // cell state [mt][nt][batch 0/1]

    // layer-1 gate biases (replace gx prefetch)
    float qb[2][4] = {};
    if (lay == 1 && pw) {
        #pragma unroll
        for (int mt = 0; mt < 2; ++mt) {
            int unit = sub * 8 + mt * 4 + r;
            #pragma unroll
            for (int g = 0; g < 4; ++g)
                qb[mt][g] = b_ih1[g * 512 + unit] + b_hh1[g * 512 + unit];
        }
    }

    for (int gen = 0; gen <= 512; ++gen) {
        grid_sync128();

        if (lay == 0) {
            if (gen == 512) continue;
            int t = gen;
            const uint8_t* s1 = (const uint8_t*)d_h1f16 + (size_t)t * SLABB;

            // gx0 prefetch (scattered; consumed only in pointwise — hides)
            float q[2][2][4][2];
            if (pw) {
                #pragma unroll
                for (int mt = 0; mt < 2; ++mt) {
                    int unit = sub * 8 + mt * 4 + r;
                    #pragma unroll
                    for (int nt = 0; nt < 2; ++nt) {
                        int b0 = w * 16 + nt * 8 + cp * 2;
                        const float* g0 = d_gx0 + ((size_t)t * B_SZ + b0) * G4 + unit;
                        #pragma unroll
                        for (int g = 0; g < 4; ++g) {
                            q[mt][nt][g][0] = g0[g * 512];
                            q[mt][nt][g][1] = g0[g * 512 + G4];
                        }
                    }
                }
            }

            #pragma unroll
            for (int qq = 0; qq < 4; ++qq) {
                #pragma unroll
                for (int i = 0; i < 8; ++i) {
                    int idx = tid + i * 128;
                    int b = idx >> 4, chl = (idx >> 2) & 3, c16 = idx & 3;
                    int ch = qq * 4 + chl;
                    uint32_t so = (uint32_t)(b * 1024 + ch * 64 + c16 * 16);
                    uint32_t dofs = ch * 4096 + swz_off(b, c16);
                    CP_ASYNC16(bB1 + dofs, s1 + so);
                }
                CP_COMMIT();
            }

            float acc[2][2][4] = {};
            #pragma unroll
            for (int qq = 0; qq < 4; ++qq) {
                if (qq == 0) CP_WAIT(3);
                else if (qq == 1) CP_WAIT(2);
                else if (qq == 2) CP_WAIT(1);
                else CP_WAIT(0);
                __syncthreads();
                #pragma unroll
                for (int chl = 0; chl < 4; ++chl) {
                    int ch = qq * 4 + chl;
                    #pragma unroll
                    for (int kk = 0; kk < 32; kk += 16) {
                        uint32_t aH[2][4], aL[2][4], rr[4];
                        ldm_x4(aH[0], frag_addr(bAh + ch * 2048, 0, kk, lane));
                        ldm_x4(aH[1], frag_addr(bAh + ch * 2048, 16, kk, lane));
                        ldm_x4(aL[0], frag_addr(bAl + ch * 2048, 0, kk, lane));
                        ldm_x4(aL[1], frag_addr(bAl + ch * 2048, 16, kk, lane));
                        uint32_t bF[2][2];
                        ldm_x4(rr, frag_addr(bB1 + ch * 4096, w * 16, kk, lane));
                        bF[0][0] = rr[0]; bF[0][1] = rr[2];
                        bF[1][0] = rr[1]; bF[1][1] = rr[3];
                        #pragma unroll
                        for (int mt = 0; mt < 2; ++mt)
                            #pragma unroll
                            for (int nt = 0; nt < 2; ++nt) {
                                hmma16(acc[mt][nt], aH[mt], bF[nt]);
                                hmma16(acc[mt][nt], aL[mt], bF[nt]);
                            }
                    }
                }
            }
            __syncthreads();

            #pragma unroll
            for (int mt = 0; mt < 2; ++mt)
                #pragma unroll
                for (int nt = 0; nt < 2; ++nt) {
                    float f0 = __shfl_xor_sync(0xffffffffu, acc[mt][nt][0], 16);
                    float f1 = __shfl_xor_sync(0xffffffffu, acc[mt][nt][1], 16);
                    float o0 = __shfl_xor_sync(0xffffffffu, acc[mt][nt][2], 16);
                    float o1 = __shfl_xor_sync(0xffffffffu, acc[mt][nt][3], 16);
                    if (pw) {
                        float gi0 = acc[mt][nt][0] + q[mt][nt][0][0];
                        float gf0 = f0              + q[mt][nt][1][0];
                        float gg0 = acc[mt][nt][2] + q[mt][nt][2][0];
                        float go0 = o0              + q[mt][nt][3][0];
                        float gi1 = acc[mt][nt][1] + q[mt][nt][0][1];
                        float gf1 = f1              + q[mt][nt][1][1];
                        float gg1 = acc[mt][nt][3] + q[mt][nt][2][1];
                        float go1 = o1              + q[mt][nt][3][1];
                        cst[mt][nt][0] = fmaf(sigm(gf0), cst[mt][nt][0], sigm(gi0) * tanh_f(gg0));
                        cst[mt][nt][1] = fmaf(sigm(gf1), cst[mt][nt][1], sigm(gi1) * tanh_f(gg1));
                        float h0 = sigm(go0) * tanh_f(cst[mt][nt][0]);
                        float h1 = sigm(go1) * tanh_f(cst[mt][nt][1]);
                        int b0 = w * 16 + nt * 8 + cp * 2;
                        int unit = sub * 8 + mt * 4 + r;
                        size_t base = (size_t)(t + 1) * 32768 + (size_t)b0 * 512 + unit;
                        d_h1f16[base]       = __float2half(h0);
                        d_h1f16[base + 512] = __float2half(h1);
                    }
                }
        } else {
            if (gen == 0) continue;
            int u = gen - 1;
            const uint8_t* s1 = (const uint8_t*)d_h1f16 + (size_t)(u + 1) * SLABB;
            const uint8_t* s2 = (const uint8_t*)d_h2f16 + (size_t)u * SLABB;

            #pragma unroll
            for (int qq = 0; qq < 4; ++qq) {
                #pragma unroll
                for (int i = 0; i < 8; ++i) {
                    int idx = tid + i * 128;
                    int b = idx >> 4, chl = (idx >> 2) & 3, c16 = idx & 3;
                    int ch = qq * 4 + chl;
                    uint32_t so = (uint32_t)(b * 1024 + ch * 64 + c16 * 16);
                    uint32_t dofs = ch * 4096 + swz_off(b, c16);
                    CP_ASYNC16(bB1 + dofs, s1 + so);
                    CP_ASYNC16(bB2 + dofs, s2 + so);
                }
                CP_COMMIT();
            }

            float acc[2][2][4] = {};
            #pragma unroll
            for (int qq = 0; qq < 4; ++qq) {
                if (qq == 0) CP_WAIT(3);
                else if (qq == 1) CP_WAIT(2);
                else if (qq == 2) CP_WAIT(1);
                else CP_WAIT(0);
                __syncthreads();
                #pragma unroll
                for (int chl = 0; chl < 4; ++chl) {
                    int ch = qq * 4 + chl;
                    #pragma unroll
                    for (int kk = 0; kk < 32; kk += 16) {
                        uint32_t aH[2][4], aL[2][4], aI[2][4], rr[4];
                        ldm_x4(aH[0], frag_addr(bAh + ch * 2048, 0, kk, lane));
                        ldm_x4(aH[1], frag_addr(bAh + ch * 2048, 16, kk, lane));
                        ldm_x4(aL[0], frag_addr(bAl + ch * 2048, 0, kk, lane));
                        ldm_x4(aL[1], frag_addr(bAl + ch * 2048, 16, kk, lane));
                        ldm_x4(aI[0], frag_addr(bAi + ch * 2048, 0, kk, lane));
                        ldm_x4(aI[1], frag_addr(bAi + ch * 2048, 16, kk, lane));
                        uint32_t b1[2][2], b2[2][2];
                        ldm_x4(rr, frag_addr(bB1 + ch * 4096, w * 16, kk, lane));
                        b1[0][0] = rr[0]; b1[0][1] = rr[2];
                        b1[1][0] = rr[1]; b1[1][1] = rr[3];
                        ldm_x4(rr, frag_addr(bB2 + ch * 4096, w * 16, kk, lane));
                        b2[0][0] = rr[0]; b2[0][1] = rr[2];
                        b2[1][0] = rr[1]; b2[1][1] = rr[3];
                        #pragma unroll
                        for (int mt = 0; mt < 2; ++mt)
                            #pragma unroll
                            for (int nt = 0; nt < 2; ++nt) {
                                hmma16(acc[mt][nt], aH[mt], b2[nt]);
                                hmma16(acc[mt][nt], aL[mt], b2[nt]);
                                hmma16(acc[mt][nt], aI[mt], b1[nt]);
                            }
                    }
                }
            }
            __syncthreads();

            #pragma unroll
            for (int mt = 0; mt < 2; ++mt)
                #pragma unroll
                for (int nt = 0; nt < 2; ++nt) {
                    float f0 = __shfl_xor_sync(0xffffffffu, acc[mt][nt][0], 16);
                    float f1 = __shfl_xor_sync(0xffffffffu, acc[mt][nt][1], 16);
                    float o0 = __shfl_xor_sync(0xffffffffu, acc[mt][nt][2], 16);
                    float o1 = __shfl_xor_sync(0xffffffffu, acc[mt][nt][3], 16);
                    if (pw) {
                        float gi0 = acc[mt][nt][0] + qb[mt][0];
                        float gf0 = f0              + qb[mt][1];
                        float gg0 = acc[mt][nt][2] + qb[mt][2];
                        float go0 = o0              + qb[mt][3];
                        float gi1 = acc[mt][nt][1] + qb[mt][0];
                        float gf1 = f1              + qb[mt][1];
                        float gg1 = acc[mt][nt][3] + qb[mt][2];
                        float go1 = o1              + qb[mt][3];
                        cst[mt][nt][0] = fmaf(sigm(gf0), cst[mt][nt][0], sigm(gi0) * tanh_f(gg0));
                        cst[mt][nt][1] = fmaf(sigm(gf1), cst[mt][nt][1], sigm(gi1) * tanh_f(gg1));
                        float h0 = sigm(go0) * tanh_f(cst[mt][nt][0]);
                        float h1 = sigm(go1) * tanh_f(cst[mt][nt][1]);
                        int b0 = w * 16 + nt * 8 + cp * 2;
                        int unit = sub * 8 + mt * 4 + r;
                        size_t base = (size_t)(u + 1) * 32768 + (size_t)b0 * 512 + unit;
                        d_h2f16[base]       = __float2half(h0);
                        d_h2f16[base + 512] = __float2half(h1);
                        __nv_bfloat16 hh0 = __float2bfloat16(h0);
                        __nv_bfloat16 hh1 = __float2bfloat16(h1);
                        d_h2hi[base]       = hh0;
                        d_h2lo[base]       = __float2bfloat16(h0 - __bfloat162float(hh0));
                        d_h2hi[base + 512] = hh1;
                        d_h2lo[base + 512] = __float2bfloat16(h1 - __bfloat162float(hh1));
                    }
                }
        }
    }
}

// ---------------------------------------------------------------------------
// KG: logits GEMM (R12-proven bf16-split mma.sync).
// out[b][t][v] = h2[t] . W_out^T + b_out
// ---------------------------------------------------------------------------
__global__ __launch_bounds__(256) void logits_mma_kernel(
    const float* __restrict__ bo, float* __restrict__ outp)
{
    __shared__ __align__(16) uint8_t sAh[8192], sAl[8192], sBh[8192], sBl[8192];

    int tid = threadIdx.x, lane = tid & 31, wid = tid >> 5;
    int mw = wid & 3, nw = wid >> 2;
    int n0 = blockIdx.x * 128, tp = blockIdx.y;

    uint32_t bAh = smem_u32(sAh), bAl = smem_u32(sAl);
    uint32_t bBh = smem_u32(sBh), bBl = smem_u32(sBl);

    const __nv_bfloat16* Ah = d_h2hi + (size_t)(2 * tp + 1) * 32768;
    const __nv_bfloat16* Al = d_h2lo + (size_t)(2 * tp + 1) * 32768;
    const __nv_bfloat16* Bh = d_Wohi + (size_t)n0 * 512;
    const __nv_bfloat16* Bl = d_Wolo + (size_t)n0 * 512;

    float acc[2][8][4] = {};

    int r0t = tid >> 2,          c0t = tid & 3;
    int r1t = (tid + 256) >> 2,  c1t = tid & 3;
    uint32_t d0 = swz_off(r0t, c0t), d1 = swz_off(r1t, c1t);

    for (int kc = 0; kc < 512; kc += 32) {
        uint4 vah0 = *(const uint4*)(Ah + (size_t)r0t * 512 + kc + c0t * 8);
        uint4 vah1 = *(const uint4*)(Ah + (size_t)r1t * 512 + kc + c1t * 8);
        uint4 val0 = *(const uint4*)(Al + (size_t)r0t * 512 + kc + c0t * 8);
        uint4 val1 = *(const uint4*)(Al + (size_t)r1t * 512 + kc + c1t * 8);
        uint4 vbh0 = *(const uint4*)(Bh + (size_t)r0t * 512 + kc + c0t * 8);
        uint4 vbh1 = *(const uint4*)(Bh + (size_t)r1t * 512 + kc + c1t * 8);
        uint4 vbl0 = *(const uint4*)(Bl + (size_t)r0t * 512 + kc + c0t * 8);
        uint4 vbl1 = *(const uint4*)(Bl + (size_t)r1t * 512 + kc + c1t * 8);

        __syncthreads();
        *(uint4*)(sAh + d0) = vah0;  *(uint4*)(sAh + d1) = vah1;
        *(uint4*)(sAl + d0) = val0;  *(uint4*)(sAl + d1) = val1;
        *(uint4*)(sBh + d0) = vbh0;  *(uint4*)(sBh + d1) = vbh1;
        *(uint4*)(sBl + d0) = vbl0;  *(uint4*)(sBl + d1) = vbl1;
        __syncthreads();

        #pragma unroll
        for (int kk = 0; kk < 32; kk += 16) {
            uint32_t aH[2][4], aL[2][4], bb[8][2];
            #pragma unroll
            for (int mt = 0; mt < 2; ++mt) {
                ldm_x4(aH[mt], frag_addr(bAh, mw * 32 + mt * 16, kk, lane));
                ldm_x4(aL[mt], frag_addr(bAl, mw * 32 + mt * 16, kk, lane));
            }
            #pragma unroll
            for (int q = 0; q < 4; ++q) {
                uint32_t rr[4];
                ldm_x4(rr, frag_addr(bBh, nw * 64 + q * 16, kk, lane));
                bb[2 * q][0] = rr[0]; bb[2 * q][1] = rr[2];
                bb[2 * q + 1][0] = rr[1]; bb[2 * q + 1][1] = rr[3];
            }
            #pragma unroll
            for (int mt = 0; mt < 2; ++mt)
                #pragma unroll
                for (int nt = 0; nt < 8; ++nt) {
                    hmma(acc[mt][nt], aH[mt], bb[nt]);
                    hmma(acc[mt][nt], aL[mt], bb[nt]);
                }
            #pragma unroll
            for (int q = 0; q < 4; ++q) {
                uint32_t rr[4];
                ldm_x4(rr, frag_addr(bBl, nw * 64 + q * 16, kk, lane));
                bb[2 * q][0] = rr[0]; bb[2 * q][1] = rr[2];
                bb[2 * q + 1][0] = rr[1]; bb[2 * q + 1][1] = rr[3];
            }
            #pragma unroll
            for (int mt = 0; mt < 2; ++mt)
                #pragma unroll
                for (int nt = 0; nt < 8; ++nt)
                    hmma(acc[mt][nt], aH[mt], bb[nt]);
        }
    }

    int gr = lane >> 2, gc2 = (lane & 3) * 2;
    #pragma unroll
    for (int mt = 0; mt < 2; ++mt) {
        #pragma unroll
        for (int half = 0; half < 2; ++half) {
            int row = mw * 32 + mt * 16 + gr + half * 8;
            int t = tp * 2 + (row >> 6), b = row & 63;
            #pragma unroll
            for (int nt = 0; nt < 8; ++nt) {
                int col = n0 + nw * 64 + nt * 8 + gc2;
                float2 st = make_float2(acc[mt][nt][half * 2 + 0] + bo[col],
                                        acc[mt][nt][half * 2 + 1] + bo[col + 1]);
                *(float2*)(outp + ((size_t)b * T_LEN + t) * 256 + col) = st;
            }
        }
    }
}

// ---------------------------------------------------------------------------
// kernel_launch
// ---------------------------------------------------------------------------
extern "C" void kernel_launch(void* const* d_in, const int* in_sizes, int n_in,
                              void* d_out, int out_size) {
    const float* ecc     = (const float*)d_in[0];
    const int*   cat     = (const int*)  d_in[1];
    const float* num     = (const float*)d_in[2];
    const int*   payload = (const int*)  d_in[3];
    const float* ce0     = (const float*)d_in[4];
    const float* ce1     = (const float*)d_in[5];
    const float* ce2     = (const float*)d_in[6];
    const float* bemb    = (const float*)d_in[7];
    const float* W_ih0   = (const float*)d_in[8];
    const float* W_hh0   = (const float*)d_in[9];
    const float* b_ih0   = (const float*)d_in[10];
    const float* b_hh0   = (const float*)d_in[11];
    const float* W_ih1   = (const float*)d_in[12];
    const float* W_hh1   = (const float*)d_in[13];
    const float* b_ih1   = (const float*)d_in[14];
    const float* b_hh1   = (const float*)d_in[15];
    const float* W_outp  = (const float*)d_in[16];
    const float* b_outp  = (const float*)d_in[17];
    float* out = (float*)d_out;

    cudaFuncSetAttribute(rec_fused_kernel,
                         cudaFuncAttributeMaxDynamicSharedMemorySize, 229376);

    zero_h0_kernel<<<64, 512>>>();
    gctx_kernel<<<64, 256>>>(ecc, cat, num, ce0, ce1, ce2, W_ih0, b_ih0, b_hh0);
    ptable_kernel<<<2080, 256>>>(bemb, W_ih0);
    gx0_kernel<<<dim3(T_LEN, B_SZ), 128>>>(payload);
    convw_out_kernel<<<512, 256>>>(W_outp);
    convwhh_kernel<<<512, 256>>>(W_hh0, 0);
    convwhh_kernel<<<512, 256>>>(W_hh1, 1);
    convwih_kernel<<<512, 256>>>(W_ih1);
    rec_fused_kernel<<<128, 128, 229376>>>(b_ih1, b_hh1);
    logits_mma_kernel<<<dim3(2, 256), 256>>>(b_outp, out);
}